// round 10
// baseline (speedup 1.0000x reference)
#include <cuda_runtime.h>
#include <float.h>
#include <math.h>

#define MAXT 8192
#define NB   128          // direction bins == grid size of mega kernel
#define CAP  128          // max key candidates per bin (expect ~2-10)
#define CAPQ 768          // fallback path only
#define BTH  512
#define NWRP (BTH / 32)
#define PD   36
#define RPB  (MAXT / NB)  // 64 rows per block

// Device scratch (graph-capturable: no allocs). All cross-launch state is
// either fully rewritten each launch (g_KK, g_V*, g_sPart*, g_n2*, g_th*),
// self-resetting (g_ccnt, g_qcnt: owning block zeroes before reuse), or
// monotone (g_bar barrier counter).
__device__ ulonglong2 g_KK[MAXT];                 // pack(Kp,Ks) per key
__device__ float g_Vop[MAXT], g_Varg[MAXT], g_Vstk[MAXT];
__device__ float g_sPartP[NB * NB], g_sPartS[NB * NB];   // [bin*NB + block]
__device__ float g_n2P[NB], g_n2S[NB];
__device__ float g_thP[NB], g_thS[NB];
__device__ int g_ccnt[2 * NB];                    // candidate counts (self-reset)
__device__ int g_candP[NB * CAP], g_candS[NB * CAP];
__device__ unsigned g_bar;
// fallback (generic shapes) only:
__device__ ulonglong2 g_QQ[MAXT];
__device__ unsigned g_binPS[MAXT];
__device__ int g_qcnt[2 * NB];
__device__ int g_qlistP[NB * CAPQ], g_qlistS[NB * CAPQ];

__device__ __forceinline__ unsigned long long packf2(float lo, float hi) {
    return ((unsigned long long)__float_as_uint(hi) << 32) | (unsigned long long)__float_as_uint(lo);
}
__device__ __forceinline__ float lo32(unsigned long long v) { return __uint_as_float((unsigned)v); }
__device__ __forceinline__ float hi32(unsigned long long v) { return __uint_as_float((unsigned)(v >> 32)); }

__device__ __forceinline__ unsigned long long mul2(unsigned long long a, unsigned long long b) {
    unsigned long long r;
    asm("mul.rn.f32x2 %0, %1, %2;" : "=l"(r) : "l"(a), "l"(b));
    return r;
}
__device__ __forceinline__ unsigned long long fma2(unsigned long long a, unsigned long long b, unsigned long long c) {
    unsigned long long r;
    asm("fma.rn.f32x2 %0, %1, %2, %3;" : "=l"(r) : "l"(a), "l"(b), "l"(c));
    return r;
}

__device__ __forceinline__ ulonglong2 ldcg_u2(const ulonglong2* p) {
    uint4 v = __ldcg((const uint4*)p);
    ulonglong2 r;
    r.x = ((unsigned long long)v.y << 32) | v.x;
    r.y = ((unsigned long long)v.w << 32) | v.z;
    return r;
}

#define PI_F 3.14159265358979f
#define TWO_PI_F 6.2831853071795865f

__device__ __forceinline__ unsigned qbins(float qpx, float qpy, float qsx, float qsy) {
    const float SC = NB / TWO_PI_F;
    int bP = (int)((atan2f(qpy, qpx) + PI_F) * SC);
    bP = min(max(bP, 0), NB - 1);
    int bS = (int)((atan2f(qsy, qsx) + PI_F) * SC);
    bS = min(max(bS, 0), NB - 1);
    return (unsigned)bP | ((unsigned)bS << 16);
}

// Device-wide barrier: valid because grid (128) <= SM count (148+): all
// blocks resident in wave 1. Cumulative counter (monotone across replays
// and across the 3 calls per launch): a block arrives (one atomicAdd),
// rounds up to the next multiple of gridDim, polls via volatile loads.
// Safe for consecutive barriers: no block can arrive at barrier N+1 until
// barrier N's full count is reached.
__device__ __forceinline__ void grid_sync() {
    __syncthreads();
    __threadfence();
    if (threadIdx.x == 0) {
        const unsigned G = gridDim.x;
        unsigned t = atomicAdd(&g_bar, 1u);
        unsigned target = (t / G + 1u) * G;
        while (*(volatile unsigned*)&g_bar < target) { __nanosleep(64); }
        __threadfence();
    }
    __syncthreads();
}

// ---------------------------------------------------------------------------
// MEGA kernel (D==36, T==MAXT). One block per direction bin AND per 64-row
// slice. Inverted dataflow: no block ever scans all T keys.
// ---------------------------------------------------------------------------
__global__ __launch_bounds__(BTH) void mega_kernel(
        const float* __restrict__ emb,
        const float* __restrict__ wqp, const float* __restrict__ wkp,
        const float* __restrict__ wvop, const float* __restrict__ wvarg,
        const float* __restrict__ wqs, const float* __restrict__ wks,
        const float* __restrict__ wvs, float* __restrict__ out) {
    __shared__ float sw[11 * PD];
    __shared__ float se[RPB * PD];
    __shared__ ulonglong2 sKxy[RPB];       // own keys  (packed P/S)
    __shared__ ulonglong2 sQx[RPB], sQy[RPB];  // own queries
    __shared__ unsigned sbin[RPB];
    __shared__ float sn2w[2][2];
    __shared__ float sredP[4], sredS[4], sredNP[4], sredNS[4];

    const int b = blockIdx.x;
    const int tid = threadIdx.x, lane = tid & 31, w = tid >> 5;
    const int T = MAXT;
    const float DLT = TWO_PI_F / NB;
    const int base = b * RPB;

    // ===== phase 1: project own 64 rows; per-bin partial maxes ==============
    for (int k = tid; k < 2 * PD; k += BTH) {
        sw[k]          = wqp[k];
        sw[2 * PD + k] = wkp[k];
        sw[4 * PD + k] = wqs[k];
        sw[6 * PD + k] = wks[k];
    }
    if (tid < PD) {
        sw[8 * PD + tid]  = wvop[tid];
        sw[9 * PD + tid]  = wvarg[tid];
        sw[10 * PD + tid] = wvs[tid];
    }
    {
        const float4* emb4 = (const float4*)(emb + (size_t)base * PD);
        if (tid < RPB * PD / 4) ((float4*)se)[tid] = emb4[tid];
        int idx = tid + BTH;
        if (idx < RPB * PD / 4) ((float4*)se)[idx] = emb4[idx];
    }
    __syncthreads();

    if (tid < RPB * 4) {
        const int row = tid >> 2, part = tid & 3;
        const float* r0 = se + row * PD + part * 9;
        float rv[9];
#pragma unroll
        for (int dd = 0; dd < 9; dd++) rv[dd] = r0[dd];
        // c: 0=Qp.x 1=Qp.y 2=Kp.x 3=Kp.y 4=Qs.x 5=Qs.y 6=Ks.x 7=Ks.y 8=Vop 9=Varg 10=Vstk
        float a[11];
#pragma unroll
        for (int c = 0; c < 11; c++) a[c] = 0.f;
#pragma unroll
        for (int c = 0; c < 11; c++) {
            const float* wc = sw + c * PD + part * 9;
#pragma unroll
            for (int dd = 0; dd < 9; dd++) a[c] = fmaf(rv[dd], wc[dd], a[c]);
        }
#pragma unroll
        for (int c = 0; c < 11; c++) {
            a[c] += __shfl_down_sync(0xffffffffu, a[c], 1);
            a[c] += __shfl_down_sync(0xffffffffu, a[c], 2);
        }
        if (part == 0) {
            int i = base + row;
            ulonglong2 kk = make_ulonglong2(packf2(a[2], a[6]), packf2(a[3], a[7]));
            g_KK[i] = kk;
            sKxy[row] = kk;
            sQx[row] = make_ulonglong2(packf2(a[0], a[4]), 0).x == 0 ? make_ulonglong2(packf2(a[0], a[4]), 0) : make_ulonglong2(packf2(a[0], a[4]), 0);
            sQx[row].x = packf2(a[0], a[4]);
            sQy[row].x = packf2(a[1], a[5]);
            sbin[row] = qbins(a[0], a[1], a[4], a[5]);
            g_Vop[i] = a[8]; g_Varg[i] = a[9]; g_Vstk[i] = a[10];
        }
    }
    __syncthreads();

    // per-bin partial max over own 64 keys, for ALL 128 bins (smem ALU only)
    {
        const int mybin = tid >> 2, q = tid & 3;
        const float thc = -PI_F + (mybin + 0.5f) * DLT;
        const float ux = cosf(thc), uy = sinf(thc);
        const unsigned long long ua = packf2(ux, ux), ub = packf2(uy, uy);
        float mP = -FLT_MAX, mS = -FLT_MAX;
#pragma unroll
        for (int k = 0; k < RPB / 4; k++) {
            ulonglong2 kk = sKxy[q * (RPB / 4) + k];
            unsigned long long s = fma2(ua, kk.x, mul2(ub, kk.y));
            mP = fmaxf(mP, lo32(s));
            mS = fmaxf(mS, hi32(s));
        }
        mP = fmaxf(mP, __shfl_down_sync(0xffffffffu, mP, 1));
        mS = fmaxf(mS, __shfl_down_sync(0xffffffffu, mS, 1));
        mP = fmaxf(mP, __shfl_down_sync(0xffffffffu, mP, 2));
        mS = fmaxf(mS, __shfl_down_sync(0xffffffffu, mS, 2));
        if (q == 0) {
            g_sPartP[mybin * NB + b] = mP;
            g_sPartS[mybin * NB + b] = mS;
        }
    }
    if (tid < RPB) {
        ulonglong2 kk = sKxy[tid];
        unsigned long long n2 = fma2(kk.x, kk.x, mul2(kk.y, kk.y));
        float np = lo32(n2), ns = hi32(n2);
#pragma unroll
        for (int off = 16; off; off >>= 1) {
            np = fmaxf(np, __shfl_xor_sync(0xffffffffu, np, off));
            ns = fmaxf(ns, __shfl_xor_sync(0xffffffffu, ns, off));
        }
        if (lane == 0) { sn2w[0][tid >> 5] = np; sn2w[1][tid >> 5] = ns; }
    }
    __syncthreads();
    if (tid == 0) {
        g_n2P[b] = fmaxf(sn2w[0][0], sn2w[0][1]);
        g_n2S[b] = fmaxf(sn2w[1][0], sn2w[1][1]);
    }

    grid_sync();   // partials + keys + V visible

    // ===== phase 2: exact threshold for own bin; reset own counters =========
    if (tid < NB) {
        float vp = g_sPartP[b * NB + tid];
        float vs = g_sPartS[b * NB + tid];
        float np = g_n2P[tid];
        float ns = g_n2S[tid];
#pragma unroll
        for (int off = 16; off; off >>= 1) {
            vp = fmaxf(vp, __shfl_xor_sync(0xffffffffu, vp, off));
            vs = fmaxf(vs, __shfl_xor_sync(0xffffffffu, vs, off));
            np = fmaxf(np, __shfl_xor_sync(0xffffffffu, np, off));
            ns = fmaxf(ns, __shfl_xor_sync(0xffffffffu, ns, off));
        }
        if (lane == 0) { sredP[w] = vp; sredS[w] = vs; sredNP[w] = np; sredNS[w] = ns; }
    }
    __syncthreads();
    if (tid == 0) {
        float MP = fmaxf(fmaxf(sredP[0], sredP[1]), fmaxf(sredP[2], sredP[3]));
        float MS = fmaxf(fmaxf(sredS[0], sredS[1]), fmaxf(sredS[2], sredS[3]));
        float NP = fmaxf(fmaxf(sredNP[0], sredNP[1]), fmaxf(sredNP[2], sredNP[3]));
        float NS = fmaxf(fmaxf(sredNS[0], sredNS[1]), fmaxf(sredNS[2], sredNS[3]));
        // Exact-cover threshold (round-4-proven): argmax key of any direction
        // in this bin has s_u >= M - Kmax*DLT; 1.25 inflation absorbs fp slop.
        g_thP[b] = MP - 1.25f * sqrtf(NP) * DLT;
        g_thS[b] = MS - 1.25f * sqrtf(NS) * DLT;
        g_ccnt[b] = 0;
        g_ccnt[NB + b] = 0;
    }

    grid_sync();   // thresholds + counter resets visible

    // ===== phase 3: test OWN keys against ALL bins; append candidates =======
    {
        const int mybin = tid >> 2, q = tid & 3;
        const float thc = -PI_F + (mybin + 0.5f) * DLT;
        const float ux = cosf(thc), uy = sinf(thc);   // identical fp to phase 1
        const unsigned long long ua = packf2(ux, ux), ub = packf2(uy, uy);
        const float tP = g_thP[mybin], tS = g_thS[mybin];
#pragma unroll
        for (int k = 0; k < RPB / 4; k++) {
            const int local = q * (RPB / 4) + k;
            ulonglong2 kk = sKxy[local];
            unsigned long long s = fma2(ua, kk.x, mul2(ub, kk.y));
            if (lo32(s) >= tP) {
                int p = atomicAdd(&g_ccnt[mybin], 1);
                if (p < CAP) g_candP[mybin * CAP + p] = base + local;
            }
            if (hi32(s) >= tS) {
                int p = atomicAdd(&g_ccnt[NB + mybin], 1);
                if (p < CAP) g_candS[mybin * CAP + p] = base + local;
            }
        }
    }

    grid_sync();   // candidate lists complete

    // ===== phase 4: resolve OWN 64 queries (both heads) ======================
    // Cross-block data (counts, lists, keys, V) read with __ldcg: L1 is not
    // coherent with other blocks' same-launch writes; L2 is.
    if (tid < 2 * RPB) {
        const int row = tid >> 1, head = tid & 1;
        const int i = base + row;
        const unsigned bp = sbin[row];
        const int bin = head ? (int)(bp >> 16) : (int)(bp & 0xffffu);
        const float qx = head ? hi32(sQx[row].x) : lo32(sQx[row].x);
        const float qy = head ? hi32(sQy[row].x) : lo32(sQy[row].x);
        const int cnt = __ldcg(&g_ccnt[head ? NB + bin : bin]);
        const int* cl = (head ? g_candS : g_candP) + bin * CAP;

        float best = -FLT_MAX; int bi = 0x7fffffff;
        if (cnt <= CAP) {
            for (int c = 0; c < cnt; c++) {
                int kj = __ldcg(&cl[c]);
                ulonglong2 k2 = ldcg_u2(&g_KK[kj]);
                float kx = head ? hi32(k2.x) : lo32(k2.x);
                float ky = head ? hi32(k2.y) : lo32(k2.y);
                float sc = fmaf(qx, kx, __fmul_rn(qy, ky));
                if (sc > best || (sc == best && kj < bi)) { best = sc; bi = kj; }
            }
        } else {
            // exact fallback (never expected): full scan, first-index semantics
            for (int j = 0; j < T; j++) {
                ulonglong2 k2 = ldcg_u2(&g_KK[j]);
                float kx = head ? hi32(k2.x) : lo32(k2.x);
                float ky = head ? hi32(k2.y) : lo32(k2.y);
                float sc = fmaf(qx, kx, __fmul_rn(qy, ky));
                if (sc > best) { best = sc; bi = j; }
            }
        }
        if (head == 0) {
            out[i]     = __ldcg(&g_Vop[bi]);
            out[T + i] = __ldcg(&g_Varg[bi]);
        } else {
            out[2 * T + i] = __ldcg(&g_Vstk[bi]);
        }
    }
}

// ---------------------------------------------------------------------------
// Generic fallback path (D != 36 or T != MAXT): R8's two-kernel pipeline.
// ---------------------------------------------------------------------------
__device__ __forceinline__ void push_query(int i, unsigned bp) {
    const int bP = (int)(bp & 0xffffu), bS = (int)(bp >> 16);
    int p = atomicAdd(&g_qcnt[bP], 1);
    if (p < CAPQ) g_qlistP[bP * CAPQ + p] = i;
    int s = atomicAdd(&g_qcnt[NB + bS], 1);
    if (s < CAPQ) g_qlistS[bS * CAPQ + s] = i;
}

__global__ void proj_generic_kernel(
        const float* __restrict__ emb,
        const float* __restrict__ wqp, const float* __restrict__ wkp,
        const float* __restrict__ wvop, const float* __restrict__ wvarg,
        const float* __restrict__ wqs, const float* __restrict__ wks,
        const float* __restrict__ wvs, int T, int D) {
    extern __shared__ float sw[];
    const int tid = threadIdx.x;
    for (int k = tid; k < 2 * D; k += blockDim.x) {
        sw[k]         = wqp[k];
        sw[2 * D + k] = wkp[k];
        sw[4 * D + k] = wqs[k];
        sw[6 * D + k] = wks[k];
    }
    for (int k = tid; k < D; k += blockDim.x) {
        sw[8 * D + k]  = wvop[k];
        sw[9 * D + k]  = wvarg[k];
        sw[10 * D + k] = wvs[k];
    }
    __syncthreads();
    int i = blockIdx.x * blockDim.x + tid;
    if (i >= T) return;
    const float* e = emb + (size_t)i * D;
    float a[11];
#pragma unroll
    for (int c = 0; c < 11; c++) a[c] = 0.f;
    for (int d = 0; d < D; d++) {
        float ev = e[d];
#pragma unroll
        for (int c = 0; c < 11; c++) a[c] = fmaf(ev, sw[c * D + d], a[c]);
    }
    g_QQ[i] = make_ulonglong2(packf2(a[0], a[4]), packf2(a[1], a[5]));
    g_KK[i] = make_ulonglong2(packf2(a[2], a[6]), packf2(a[3], a[7]));
    unsigned bp = qbins(a[0], a[1], a[4], a[5]);
    g_binPS[i] = bp;
    g_Vop[i] = a[8]; g_Varg[i] = a[9]; g_Vstk[i] = a[10];
    push_query(i, bp);
}

__global__ __launch_bounds__(BTH) void build_query_kernel(float* __restrict__ out, int T) {
    __shared__ int scandP[CAP], scandS[CAP];
    __shared__ float sVop[CAP], sVarg[CAP], sVstk[CAP];
    __shared__ int scnt[2];
    __shared__ float sred[4][NWRP];
    __shared__ float sth[2];

    const int b = blockIdx.x;
    const int tid = threadIdx.x, lane = tid & 31, w = tid >> 5;
    const float DLT = TWO_PI_F / NB;
    const float thb = -PI_F + (b + 0.5f) * DLT;
    const float ux = cosf(thb), uy = sinf(thb);
    const unsigned long long ua = packf2(ux, ux), ub = packf2(uy, uy);

    float v[4] = {-FLT_MAX, -FLT_MAX, 0.f, 0.f};
#pragma unroll 4
    for (int j = tid; j < T; j += BTH) {
        ulonglong2 kk = g_KK[j];
        unsigned long long s  = fma2(ua, kk.x, mul2(ub, kk.y));
        unsigned long long n2 = fma2(kk.x, kk.x, mul2(kk.y, kk.y));
        v[0] = fmaxf(v[0], lo32(s));  v[1] = fmaxf(v[1], hi32(s));
        v[2] = fmaxf(v[2], lo32(n2)); v[3] = fmaxf(v[3], hi32(n2));
    }
#pragma unroll
    for (int c = 0; c < 4; c++) {
#pragma unroll
        for (int off = 16; off; off >>= 1)
            v[c] = fmaxf(v[c], __shfl_xor_sync(0xffffffffu, v[c], off));
        if (lane == 0) sred[c][w] = v[c];
    }
    if (tid < 2) scnt[tid] = 0;
    __syncthreads();
    if (tid < 2) {
        float M = sred[tid][0], N2 = sred[2 + tid][0];
#pragma unroll
        for (int k = 1; k < NWRP; k++) {
            M = fmaxf(M, sred[tid][k]);
            N2 = fmaxf(N2, sred[2 + tid][k]);
        }
        sth[tid] = M - 1.25f * sqrtf(N2) * DLT;
    }
    __syncthreads();
    const float tP = sth[0], tS = sth[1];

#pragma unroll 4
    for (int j = tid; j < T; j += BTH) {
        ulonglong2 kk = g_KK[j];
        unsigned long long s = fma2(ua, kk.x, mul2(ub, kk.y));
        if (lo32(s) >= tP) { int p = atomicAdd(&scnt[0], 1); if (p < CAP) scandP[p] = j; }
        if (hi32(s) >= tS) { int p = atomicAdd(&scnt[1], 1); if (p < CAP) scandS[p] = j; }
    }
    __syncthreads();
    const int nP = min(scnt[0], CAP), nS = min(scnt[1], CAP);
    for (int t = tid; t < nP; t += BTH) {
        int c = scandP[t];
        sVop[t] = g_Vop[c]; sVarg[t] = g_Varg[c];
    }
    for (int t = tid; t < nS; t += BTH) sVstk[t] = g_Vstk[scandS[t]];
    __syncthreads();

    const int totP = g_qcnt[b], totS = g_qcnt[NB + b];
    const int nqP = min(totP, CAPQ), nqS = min(totS, CAPQ);

    for (int t = tid; t < nqP; t += BTH) {
        const int i = g_qlistP[b * CAPQ + t];
        ulonglong2 q = g_QQ[i];
        const float qx = lo32(q.x), qy = lo32(q.y);
        float best = -FLT_MAX; int bi = 0x7fffffff, bt = 0;
        for (int c = 0; c < nP; c++) {
            int kj = scandP[c];
            ulonglong2 k2 = g_KK[kj];
            float sc = fmaf(qx, lo32(k2.x), __fmul_rn(qy, lo32(k2.y)));
            if (sc > best || (sc == best && kj < bi)) { best = sc; bi = kj; bt = c; }
        }
        out[i]     = sVop[bt];
        out[T + i] = sVarg[bt];
    }
    for (int t = tid; t < nqS; t += BTH) {
        const int i = g_qlistS[b * CAPQ + t];
        ulonglong2 q = g_QQ[i];
        const float qx = hi32(q.x), qy = hi32(q.y);
        float best = -FLT_MAX; int bi = 0x7fffffff, bt = 0;
        for (int c = 0; c < nS; c++) {
            int kj = scandS[c];
            ulonglong2 k2 = g_KK[kj];
            float sc = fmaf(qx, hi32(k2.x), __fmul_rn(qy, hi32(k2.y)));
            if (sc > best || (sc == best && kj < bi)) { best = sc; bi = kj; bt = c; }
        }
        out[2 * T + i] = sVstk[bt];
    }

    if (totP > CAPQ) {
        for (int j = tid; j < T; j += BTH) {
            if ((g_binPS[j] & 0xffffu) == (unsigned)b) {
                ulonglong2 q = g_QQ[j];
                const float qx = lo32(q.x), qy = lo32(q.y);
                float best = -FLT_MAX; int bi = 0x7fffffff, bt = 0;
                for (int c = 0; c < nP; c++) {
                    int kj = scandP[c];
                    ulonglong2 k2 = g_KK[kj];
                    float sc = fmaf(qx, lo32(k2.x), __fmul_rn(qy, lo32(k2.y)));
                    if (sc > best || (sc == best && kj < bi)) { best = sc; bi = kj; bt = c; }
                }
                out[j]     = sVop[bt];
                out[T + j] = sVarg[bt];
            }
        }
    }
    if (totS > CAPQ) {
        for (int j = tid; j < T; j += BTH) {
            if ((g_binPS[j] >> 16) == (unsigned)b) {
                ulonglong2 q = g_QQ[j];
                const float qx = hi32(q.x), qy = hi32(q.y);
                float best = -FLT_MAX; int bi = 0x7fffffff, bt = 0;
                for (int c = 0; c < nS; c++) {
                    int kj = scandS[c];
                    ulonglong2 k2 = g_KK[kj];
                    float sc = fmaf(qx, hi32(k2.x), __fmul_rn(qy, hi32(k2.y)));
                    if (sc > best || (sc == best && kj < bi)) { best = sc; bi = kj; bt = c; }
                }
                out[2 * T + j] = sVstk[bt];
            }
        }
    }

    __syncthreads();
    if (tid == 0) { g_qcnt[b] = 0; g_qcnt[NB + b] = 0; }
}

extern "C" void kernel_launch(void* const* d_in, const int* in_sizes, int n_in,
                              void* d_out, int out_size) {
    const float* emb   = (const float*)d_in[0];
    const float* wqp   = (const float*)d_in[1];
    const float* wkp   = (const float*)d_in[2];
    const float* wvop  = (const float*)d_in[3];
    const float* wvarg = (const float*)d_in[4];
    const float* wqs   = (const float*)d_in[5];
    const float* wks   = (const float*)d_in[6];
    const float* wvs   = (const float*)d_in[7];
    float* out = (float*)d_out;

    const int D = in_sizes[1] / 2;   // WQ_prog is (2, D)
    const int T = in_sizes[0] / D;   // embeddings is (T, D)

    if (D == PD && T == MAXT) {
        mega_kernel<<<NB, BTH>>>(emb, wqp, wkp, wvop, wvarg, wqs, wks, wvs, out);
    } else {
        const int pb = (T + 255) / 256;
        proj_generic_kernel<<<pb, 256, (size_t)(11 * D) * sizeof(float)>>>(
            emb, wqp, wkp, wvop, wvarg, wqs, wks, wvs, T, D);
        build_query_kernel<<<NB, BTH>>>(out, T);
    }
}

// round 11
// speedup vs baseline: 1.0980x; 1.0980x over previous
#include <cuda_runtime.h>
#include <float.h>
#include <math.h>

#define MAXT 8192
#define NB   128          // direction bins
#define CAP  128          // max key candidates per bin (expect ~2-10)
#define CAPQ 768          // max queries per bin list (expect ~64; exact fallback)
#define PD   36
#define RPB  (MAXT / NB)  // 64 rows per K1 block
#define K1TH 512
#define K2TH 1024

// Device scratch (graph-capturable: no allocs). g_qcnt self-resets (K2
// zeroes its own bins after reading, zero-initialized at load); all other
// arrays fully rewritten by K1 each launch before K2 reads them.
__device__ ulonglong2 g_QQ[MAXT], g_KK[MAXT];
__device__ unsigned g_binPS[MAXT];
__device__ float g_Vop[MAXT], g_Varg[MAXT], g_Vstk[MAXT];
__device__ float g_sPartP[NB * NB], g_sPartS[NB * NB];   // [bin*NB + block]
__device__ float g_n2P[NB], g_n2S[NB];                   // per-block |k|^2 max
__device__ int g_qcnt[2 * NB];
__device__ int g_qlistP[NB * CAPQ], g_qlistS[NB * CAPQ];

__device__ __forceinline__ unsigned long long packf2(float lo, float hi) {
    return ((unsigned long long)__float_as_uint(hi) << 32) | (unsigned long long)__float_as_uint(lo);
}
__device__ __forceinline__ float lo32(unsigned long long v) { return __uint_as_float((unsigned)v); }
__device__ __forceinline__ float hi32(unsigned long long v) { return __uint_as_float((unsigned)(v >> 32)); }

// sm_103a packed fp32 pair math (PTX-only; ptxas won't auto-fuse).
__device__ __forceinline__ unsigned long long mul2(unsigned long long a, unsigned long long b) {
    unsigned long long r;
    asm("mul.rn.f32x2 %0, %1, %2;" : "=l"(r) : "l"(a), "l"(b));
    return r;
}
__device__ __forceinline__ unsigned long long fma2(unsigned long long a, unsigned long long b, unsigned long long c) {
    unsigned long long r;
    asm("fma.rn.f32x2 %0, %1, %2, %3;" : "=l"(r) : "l"(a), "l"(b), "l"(c));
    return r;
}

#define PI_F 3.14159265358979f
#define TWO_PI_F 6.2831853071795865f

__device__ __forceinline__ unsigned qbins(float qpx, float qpy, float qsx, float qsy) {
    const float SC = NB / TWO_PI_F;
    int bP = (int)((atan2f(qpy, qpx) + PI_F) * SC);
    bP = min(max(bP, 0), NB - 1);
    int bS = (int)((atan2f(qsy, qsx) + PI_F) * SC);
    bS = min(max(bS, 0), NB - 1);
    return (unsigned)bP | ((unsigned)bS << 16);
}

__device__ __forceinline__ void push_query(int i, unsigned bp) {
    const int bP = (int)(bp & 0xffffu), bS = (int)(bp >> 16);
    int p = atomicAdd(&g_qcnt[bP], 1);
    if (p < CAPQ) g_qlistP[bP * CAPQ + p] = i;
    int s = atomicAdd(&g_qcnt[NB + bS], 1);
    if (s < CAPQ) g_qlistS[bS * CAPQ + s] = i;
}

// ---------------------------------------------------------------------------
// K1: project 64 rows per block; push per-bin query lists; compute per-bin
// partial directional maxes over OWN keys for ALL 128 bins (smem ALU, rides
// in the DRAM-latency shadow) + per-block |k|^2 max.
// ---------------------------------------------------------------------------
__global__ __launch_bounds__(K1TH) void proj_part_kernel(
        const float* __restrict__ emb,
        const float* __restrict__ wqp, const float* __restrict__ wkp,
        const float* __restrict__ wvop, const float* __restrict__ wvarg,
        const float* __restrict__ wqs, const float* __restrict__ wks,
        const float* __restrict__ wvs) {
    __shared__ float sw[11 * PD];
    __shared__ float se[RPB * PD];
    __shared__ ulonglong2 sKxy[RPB];
    __shared__ float sn2w[2][2];

    const int b = blockIdx.x;
    const int tid = threadIdx.x, lane = tid & 31;
    const float DLT = TWO_PI_F / NB;
    const int base = b * RPB;

    for (int k = tid; k < 2 * PD; k += K1TH) {
        sw[k]          = wqp[k];
        sw[2 * PD + k] = wkp[k];
        sw[4 * PD + k] = wqs[k];
        sw[6 * PD + k] = wks[k];
    }
    if (tid < PD) {
        sw[8 * PD + tid]  = wvop[tid];
        sw[9 * PD + tid]  = wvarg[tid];
        sw[10 * PD + tid] = wvs[tid];
    }
    {
        const float4* emb4 = (const float4*)(emb + (size_t)base * PD);
        if (tid < RPB * PD / 4) ((float4*)se)[tid] = emb4[tid];     // 512 of 576
        int idx = tid + K1TH;
        if (idx < RPB * PD / 4) ((float4*)se)[idx] = emb4[idx];     // last 64
    }
    __syncthreads();

    if (tid < RPB * 4) {
        const int row = tid >> 2, part = tid & 3;
        const float* r0 = se + row * PD + part * 9;
        float rv[9];
#pragma unroll
        for (int dd = 0; dd < 9; dd++) rv[dd] = r0[dd];
        // c: 0=Qp.x 1=Qp.y 2=Kp.x 3=Kp.y 4=Qs.x 5=Qs.y 6=Ks.x 7=Ks.y 8=Vop 9=Varg 10=Vstk
        float a[11];
#pragma unroll
        for (int c = 0; c < 11; c++) a[c] = 0.f;
#pragma unroll
        for (int c = 0; c < 11; c++) {
            const float* wc = sw + c * PD + part * 9;
#pragma unroll
            for (int dd = 0; dd < 9; dd++) a[c] = fmaf(rv[dd], wc[dd], a[c]);
        }
#pragma unroll
        for (int c = 0; c < 11; c++) {
            a[c] += __shfl_down_sync(0xffffffffu, a[c], 1);
            a[c] += __shfl_down_sync(0xffffffffu, a[c], 2);
        }
        if (part == 0) {
            int i = base + row;
            ulonglong2 kk = make_ulonglong2(packf2(a[2], a[6]), packf2(a[3], a[7]));
            g_QQ[i] = make_ulonglong2(packf2(a[0], a[4]), packf2(a[1], a[5]));
            g_KK[i] = kk;
            sKxy[row] = kk;
            unsigned bp = qbins(a[0], a[1], a[4], a[5]);
            g_binPS[i] = bp;
            g_Vop[i] = a[8]; g_Varg[i] = a[9]; g_Vstk[i] = a[10];
            push_query(i, bp);
        }
    }
    __syncthreads();

    // per-bin partial max over own 64 keys, ALL 128 bins: 512 thr = 128x4
    {
        const int mybin = tid >> 2, q = tid & 3;
        const float thc = -PI_F + (mybin + 0.5f) * DLT;
        const float ux = cosf(thc), uy = sinf(thc);
        const unsigned long long ua = packf2(ux, ux), ub = packf2(uy, uy);
        float mP = -FLT_MAX, mS = -FLT_MAX;
#pragma unroll
        for (int k = 0; k < RPB / 4; k++) {
            ulonglong2 kk = sKxy[q * (RPB / 4) + k];
            unsigned long long s = fma2(ua, kk.x, mul2(ub, kk.y));
            mP = fmaxf(mP, lo32(s));
            mS = fmaxf(mS, hi32(s));
        }
        mP = fmaxf(mP, __shfl_down_sync(0xffffffffu, mP, 1));
        mS = fmaxf(mS, __shfl_down_sync(0xffffffffu, mS, 1));
        mP = fmaxf(mP, __shfl_down_sync(0xffffffffu, mP, 2));
        mS = fmaxf(mS, __shfl_down_sync(0xffffffffu, mS, 2));
        if (q == 0) {
            g_sPartP[mybin * NB + b] = mP;
            g_sPartS[mybin * NB + b] = mS;
        }
    }
    // per-block |k|^2 max (both heads)
    if (tid < RPB) {
        ulonglong2 kk = sKxy[tid];
        unsigned long long n2 = fma2(kk.x, kk.x, mul2(kk.y, kk.y));
        float np = lo32(n2), ns = hi32(n2);
#pragma unroll
        for (int off = 16; off; off >>= 1) {
            np = fmaxf(np, __shfl_xor_sync(0xffffffffu, np, off));
            ns = fmaxf(ns, __shfl_xor_sync(0xffffffffu, ns, off));
        }
        if (lane == 0) { sn2w[0][tid >> 5] = np; sn2w[1][tid >> 5] = ns; }
    }
    __syncthreads();
    if (tid == 0) {
        g_n2P[b] = fmaxf(sn2w[0][0], sn2w[0][1]);
        g_n2S[b] = fmaxf(sn2w[1][0], sn2w[1][1]);
    }
}

// ---------------------------------------------------------------------------
// K2: one block per bin, 1024 threads.
//  A: reduce 128 partials -> exact global max M, Kmax^2 -> threshold
//     M - 1.25*Kmax*DLT (identical value & construction to the passing
//     R6/R8 kernels: max-of-maxes == full-scan max, same fp ops).
//  B: ONE full-T collect scan; each thread loads its 8 keys in a single
//     MLP-8 burst (1024*8 == T) -> ~one L2 latency round.
//  C: prefetch candidate K/V to smem; resolve this bin's queries from the
//     K1 qlists with exact fp32 scores + first-index tie-break.
//  Self-resets g_qcnt at the end. Exact fallback if a qlist overflowed.
// ---------------------------------------------------------------------------
__global__ __launch_bounds__(K2TH) void bin_query_kernel(float* __restrict__ out, int T) {
    __shared__ int scandP[CAP], scandS[CAP];
    __shared__ ulonglong2 sKP[CAP], sKS[CAP];
    __shared__ float sVop[CAP], sVarg[CAP], sVstk[CAP];
    __shared__ int scnt[2];
    __shared__ float sredP[4], sredS[4], sredNP[4], sredNS[4];
    __shared__ float sth[2];

    const int b = blockIdx.x;
    const int tid = threadIdx.x, lane = tid & 31, w = tid >> 5;
    const float DLT = TWO_PI_F / NB;
    const float thb = -PI_F + (b + 0.5f) * DLT;
    const float ux = cosf(thb), uy = sinf(thb);
    const unsigned long long ua = packf2(ux, ux), ub = packf2(uy, uy);

    // ---- A: threshold from partials ----
    if (tid < 2) scnt[tid] = 0;
    if (tid < NB) {
        float vp = g_sPartP[b * NB + tid];
        float vs = g_sPartS[b * NB + tid];
        float np = g_n2P[tid];
        float ns = g_n2S[tid];
#pragma unroll
        for (int off = 16; off; off >>= 1) {
            vp = fmaxf(vp, __shfl_xor_sync(0xffffffffu, vp, off));
            vs = fmaxf(vs, __shfl_xor_sync(0xffffffffu, vs, off));
            np = fmaxf(np, __shfl_xor_sync(0xffffffffu, np, off));
            ns = fmaxf(ns, __shfl_xor_sync(0xffffffffu, ns, off));
        }
        if (lane == 0) { sredP[w] = vp; sredS[w] = vs; sredNP[w] = np; sredNS[w] = ns; }
    }
    __syncthreads();
    if (tid == 0) {
        float MP = fmaxf(fmaxf(sredP[0], sredP[1]), fmaxf(sredP[2], sredP[3]));
        float MS = fmaxf(fmaxf(sredS[0], sredS[1]), fmaxf(sredS[2], sredS[3]));
        float NP = fmaxf(fmaxf(sredNP[0], sredNP[1]), fmaxf(sredNP[2], sredNP[3]));
        float NS = fmaxf(fmaxf(sredNS[0], sredNS[1]), fmaxf(sredNS[2], sredNS[3]));
        // Exact-cover threshold (proven in rounds 4/6/7/8): the argmax key of
        // ANY query direction in this bin satisfies s_u >= M - Kmax*DLT;
        // the 1.25 inflation absorbs fp slop.
        sth[0] = MP - 1.25f * sqrtf(NP) * DLT;
        sth[1] = MS - 1.25f * sqrtf(NS) * DLT;
    }
    __syncthreads();
    const float tP = sth[0], tS = sth[1];

    // ---- B: single collect scan, one MLP-8 burst per thread ----
    {
        ulonglong2 kb[8];
#pragma unroll
        for (int u = 0; u < 8; u++) {
            int j = tid + u * K2TH;
            kb[u] = (j < T) ? g_KK[j] : make_ulonglong2(0, 0);
        }
#pragma unroll
        for (int u = 0; u < 8; u++) {
            int j = tid + u * K2TH;
            if (j < T) {
                unsigned long long s = fma2(ua, kb[u].x, mul2(ub, kb[u].y));
                if (lo32(s) >= tP) { int p = atomicAdd(&scnt[0], 1); if (p < CAP) scandP[p] = j; }
                if (hi32(s) >= tS) { int p = atomicAdd(&scnt[1], 1); if (p < CAP) scandS[p] = j; }
            }
        }
    }
    __syncthreads();
    const int nP = min(scnt[0], CAP), nS = min(scnt[1], CAP);
    for (int t = tid; t < nP; t += K2TH) {
        int c = scandP[t];
        sKP[t] = g_KK[c]; sVop[t] = g_Vop[c]; sVarg[t] = g_Varg[c];
    }
    for (int t = tid; t < nS; t += K2TH) {
        int c = scandS[t];
        sKS[t] = g_KK[c]; sVstk[t] = g_Vstk[c];
    }
    __syncthreads();

    // ---- C: resolve this bin's queries ----
    const int totP = g_qcnt[b], totS = g_qcnt[NB + b];
    const int nqP = min(totP, CAPQ), nqS = min(totS, CAPQ);

    for (int t = tid; t < nqP; t += K2TH) {
        const int i = g_qlistP[b * CAPQ + t];
        ulonglong2 q = g_QQ[i];
        const float qx = lo32(q.x), qy = lo32(q.y);
        float best = -FLT_MAX; int bi = 0x7fffffff, bt = 0;
        for (int c = 0; c < nP; c++) {
            int kj = scandP[c];
            ulonglong2 k2 = sKP[c];
            float sc = fmaf(qx, lo32(k2.x), __fmul_rn(qy, lo32(k2.y)));
            if (sc > best || (sc == best && kj < bi)) { best = sc; bi = kj; bt = c; }
        }
        out[i]     = sVop[bt];
        out[T + i] = sVarg[bt];
    }
    for (int t = tid; t < nqS; t += K2TH) {
        const int i = g_qlistS[b * CAPQ + t];
        ulonglong2 q = g_QQ[i];
        const float qx = hi32(q.x), qy = hi32(q.y);
        float best = -FLT_MAX; int bi = 0x7fffffff, bt = 0;
        for (int c = 0; c < nS; c++) {
            int kj = scandS[c];
            ulonglong2 k2 = sKS[c];
            float sc = fmaf(qx, hi32(k2.x), __fmul_rn(qy, hi32(k2.y)));
            if (sc > best || (sc == best && kj < bi)) { best = sc; bi = kj; bt = c; }
        }
        out[2 * T + i] = sVstk[bt];
    }

    // exact fallback if a query list overflowed (never expected; idempotent)
    if (totP > CAPQ) {
        for (int j = tid; j < T; j += K2TH) {
            if ((g_binPS[j] & 0xffffu) == (unsigned)b) {
                ulonglong2 q = g_QQ[j];
                const float qx = lo32(q.x), qy = lo32(q.y);
                float best = -FLT_MAX; int bi = 0x7fffffff, bt = 0;
                for (int c = 0; c < nP; c++) {
                    int kj = scandP[c];
                    ulonglong2 k2 = sKP[c];
                    float sc = fmaf(qx, lo32(k2.x), __fmul_rn(qy, lo32(k2.y)));
                    if (sc > best || (sc == best && kj < bi)) { best = sc; bi = kj; bt = c; }
                }
                out[j]     = sVop[bt];
                out[T + j] = sVarg[bt];
            }
        }
    }
    if (totS > CAPQ) {
        for (int j = tid; j < T; j += K2TH) {
            if ((g_binPS[j] >> 16) == (unsigned)b) {
                ulonglong2 q = g_QQ[j];
                const float qx = hi32(q.x), qy = hi32(q.y);
                float best = -FLT_MAX; int bi = 0x7fffffff, bt = 0;
                for (int c = 0; c < nS; c++) {
                    int kj = scandS[c];
                    ulonglong2 k2 = sKS[c];
                    float sc = fmaf(qx, hi32(k2.x), __fmul_rn(qy, hi32(k2.y)));
                    if (sc > best || (sc == best && kj < bi)) { best = sc; bi = kj; bt = c; }
                }
                out[2 * T + j] = sVstk[bt];
            }
        }
    }

    __syncthreads();
    if (tid == 0) { g_qcnt[b] = 0; g_qcnt[NB + b] = 0; }   // self-reset
}

// ---------------------------------------------------------------------------
// Generic fallback (D != 36 or T != MAXT): projection + brute-force argmax.
// Simple and exact; benchmark shape never takes this path.
// ---------------------------------------------------------------------------
__global__ void proj_generic_kernel(
        const float* __restrict__ emb,
        const float* __restrict__ wqp, const float* __restrict__ wkp,
        const float* __restrict__ wvop, const float* __restrict__ wvarg,
        const float* __restrict__ wqs, const float* __restrict__ wks,
        const float* __restrict__ wvs, int T, int D) {
    extern __shared__ float sw[];
    const int tid = threadIdx.x;
    for (int k = tid; k < 2 * D; k += blockDim.x) {
        sw[k]         = wqp[k];
        sw[2 * D + k] = wkp[k];
        sw[4 * D + k] = wqs[k];
        sw[6 * D + k] = wks[k];
    }
    for (int k = tid; k < D; k += blockDim.x) {
        sw[8 * D + k]  = wvop[k];
        sw[9 * D + k]  = wvarg[k];
        sw[10 * D + k] = wvs[k];
    }
    __syncthreads();
    int i = blockIdx.x * blockDim.x + tid;
    if (i >= T) return;
    const float* e = emb + (size_t)i * D;
    float a[11];
#pragma unroll
    for (int c = 0; c < 11; c++) a[c] = 0.f;
    for (int d = 0; d < D; d++) {
        float ev = e[d];
#pragma unroll
        for (int c = 0; c < 11; c++) a[c] = fmaf(ev, sw[c * D + d], a[c]);
    }
    g_QQ[i] = make_ulonglong2(packf2(a[0], a[4]), packf2(a[1], a[5]));
    g_KK[i] = make_ulonglong2(packf2(a[2], a[6]), packf2(a[3], a[7]));
    g_Vop[i] = a[8]; g_Varg[i] = a[9]; g_Vstk[i] = a[10];
}

__global__ void brute_generic_kernel(float* __restrict__ out, int T) {
    const int gidx = blockIdx.x * blockDim.x + threadIdx.x;
    const int i = gidx >> 1, head = gidx & 1;
    if (i >= T) return;
    ulonglong2 q = g_QQ[i];
    const float qx = head ? hi32(q.x) : lo32(q.x);
    const float qy = head ? hi32(q.y) : lo32(q.y);
    float best = -FLT_MAX; int bi = 0;
    for (int j = 0; j < T; j++) {
        ulonglong2 k2 = g_KK[j];
        float kx = head ? hi32(k2.x) : lo32(k2.x);
        float ky = head ? hi32(k2.y) : lo32(k2.y);
        float sc = fmaf(qx, kx, __fmul_rn(qy, ky));
        if (sc > best) { best = sc; bi = j; }
    }
    if (head == 0) {
        out[i]     = g_Vop[bi];
        out[T + i] = g_Varg[bi];
    } else {
        out[2 * T + i] = g_Vstk[bi];
    }
}

extern "C" void kernel_launch(void* const* d_in, const int* in_sizes, int n_in,
                              void* d_out, int out_size) {
    const float* emb   = (const float*)d_in[0];
    const float* wqp   = (const float*)d_in[1];
    const float* wkp   = (const float*)d_in[2];
    const float* wvop  = (const float*)d_in[3];
    const float* wvarg = (const float*)d_in[4];
    const float* wqs   = (const float*)d_in[5];
    const float* wks   = (const float*)d_in[6];
    const float* wvs   = (const float*)d_in[7];
    float* out = (float*)d_out;

    const int D = in_sizes[1] / 2;   // WQ_prog is (2, D)
    const int T = in_sizes[0] / D;   // embeddings is (T, D)

    if (D == PD && T == MAXT) {
        proj_part_kernel<<<NB, K1TH>>>(emb, wqp, wkp, wvop, wvarg, wqs, wks, wvs);
        bin_query_kernel<<<NB, K2TH>>>(out, T);
    } else {
        const int pb = (T + 255) / 256;
        proj_generic_kernel<<<pb, 256, (size_t)(11 * D) * sizeof(float)>>>(
            emb, wqp, wkp, wvop, wvarg, wqs, wks, wvs, T, D);
        brute_generic_kernel<<<(2 * T + 255) / 256, 256>>>(out, T);
    }
}

// round 12
// speedup vs baseline: 1.1115x; 1.0122x over previous
#include <cuda_runtime.h>
#include <float.h>
#include <math.h>

#define MAXT 8192
#define NB   128          // direction bins
#define CAP  128          // max key candidates per bin (expect ~2-10)
#define CAPQ 768          // max queries per bin list (expect ~64; exact fallback)
#define PD   36
#define RPB  (MAXT / NB)  // 64 rows per K1 block
#define K1TH 512
#define K2TH 512

// Device scratch (graph-capturable: no allocs). g_qcnt self-resets (K2
// zeroes its own bins after reading; zero-initialized at load); all other
// arrays fully rewritten by K1 each launch before K2 reads them.
__device__ ulonglong2 g_QQ[MAXT], g_KK[MAXT];
__device__ unsigned g_binPS[MAXT];
__device__ float g_Vop[MAXT], g_Varg[MAXT], g_Vstk[MAXT];
__device__ float g_sPartP[NB * NB], g_sPartS[NB * NB];   // [bin*NB + block]
__device__ float g_n2P[NB], g_n2S[NB];                   // per-block |k|^2 max
__device__ int g_qcnt[2 * NB];
__device__ int g_qlistP[NB * CAPQ], g_qlistS[NB * CAPQ];

__device__ __forceinline__ unsigned long long packf2(float lo, float hi) {
    return ((unsigned long long)__float_as_uint(hi) << 32) | (unsigned long long)__float_as_uint(lo);
}
__device__ __forceinline__ float lo32(unsigned long long v) { return __uint_as_float((unsigned)v); }
__device__ __forceinline__ float hi32(unsigned long long v) { return __uint_as_float((unsigned)(v >> 32)); }

// sm_103a packed fp32 pair math (PTX-only; ptxas won't auto-fuse).
__device__ __forceinline__ unsigned long long mul2(unsigned long long a, unsigned long long b) {
    unsigned long long r;
    asm("mul.rn.f32x2 %0, %1, %2;" : "=l"(r) : "l"(a), "l"(b));
    return r;
}
__device__ __forceinline__ unsigned long long fma2(unsigned long long a, unsigned long long b, unsigned long long c) {
    unsigned long long r;
    asm("fma.rn.f32x2 %0, %1, %2, %3;" : "=l"(r) : "l"(a), "l"(b), "l"(c));
    return r;
}

#define PI_F 3.14159265358979f
#define TWO_PI_F 6.2831853071795865f

__device__ __forceinline__ unsigned qbins(float qpx, float qpy, float qsx, float qsy) {
    const float SC = NB / TWO_PI_F;
    int bP = (int)((atan2f(qpy, qpx) + PI_F) * SC);
    bP = min(max(bP, 0), NB - 1);
    int bS = (int)((atan2f(qsy, qsx) + PI_F) * SC);
    bS = min(max(bS, 0), NB - 1);
    return (unsigned)bP | ((unsigned)bS << 16);
}

__device__ __forceinline__ void push_query(int i, unsigned bp) {
    const int bP = (int)(bp & 0xffffu), bS = (int)(bp >> 16);
    int p = atomicAdd(&g_qcnt[bP], 1);
    if (p < CAPQ) g_qlistP[bP * CAPQ + p] = i;
    int s = atomicAdd(&g_qcnt[NB + bS], 1);
    if (s < CAPQ) g_qlistS[bS * CAPQ + s] = i;
}

// ---------------------------------------------------------------------------
// K1 (unchanged from R11, measured-good): project 64 rows per block; push
// per-bin query lists; per-bin partial directional maxes over OWN keys for
// ALL 128 bins (smem ALU in the DRAM-latency shadow) + per-block |k|^2 max.
// ---------------------------------------------------------------------------
__global__ __launch_bounds__(K1TH) void proj_part_kernel(
        const float* __restrict__ emb,
        const float* __restrict__ wqp, const float* __restrict__ wkp,
        const float* __restrict__ wvop, const float* __restrict__ wvarg,
        const float* __restrict__ wqs, const float* __restrict__ wks,
        const float* __restrict__ wvs) {
    __shared__ float sw[11 * PD];
    __shared__ float se[RPB * PD];
    __shared__ ulonglong2 sKxy[RPB];
    __shared__ float sn2w[2][2];

    const int b = blockIdx.x;
    const int tid = threadIdx.x, lane = tid & 31;
    const float DLT = TWO_PI_F / NB;
    const int base = b * RPB;

    for (int k = tid; k < 2 * PD; k += K1TH) {
        sw[k]          = wqp[k];
        sw[2 * PD + k] = wkp[k];
        sw[4 * PD + k] = wqs[k];
        sw[6 * PD + k] = wks[k];
    }
    if (tid < PD) {
        sw[8 * PD + tid]  = wvop[tid];
        sw[9 * PD + tid]  = wvarg[tid];
        sw[10 * PD + tid] = wvs[tid];
    }
    {
        const float4* emb4 = (const float4*)(emb + (size_t)base * PD);
        if (tid < RPB * PD / 4) ((float4*)se)[tid] = emb4[tid];
        int idx = tid + K1TH;
        if (idx < RPB * PD / 4) ((float4*)se)[idx] = emb4[idx];
    }
    __syncthreads();

    if (tid < RPB * 4) {
        const int row = tid >> 2, part = tid & 3;
        const float* r0 = se + row * PD + part * 9;
        float rv[9];
#pragma unroll
        for (int dd = 0; dd < 9; dd++) rv[dd] = r0[dd];
        // c: 0=Qp.x 1=Qp.y 2=Kp.x 3=Kp.y 4=Qs.x 5=Qs.y 6=Ks.x 7=Ks.y 8=Vop 9=Varg 10=Vstk
        float a[11];
#pragma unroll
        for (int c = 0; c < 11; c++) a[c] = 0.f;
#pragma unroll
        for (int c = 0; c < 11; c++) {
            const float* wc = sw + c * PD + part * 9;
#pragma unroll
            for (int dd = 0; dd < 9; dd++) a[c] = fmaf(rv[dd], wc[dd], a[c]);
        }
#pragma unroll
        for (int c = 0; c < 11; c++) {
            a[c] += __shfl_down_sync(0xffffffffu, a[c], 1);
            a[c] += __shfl_down_sync(0xffffffffu, a[c], 2);
        }
        if (part == 0) {
            int i = base + row;
            ulonglong2 kk = make_ulonglong2(packf2(a[2], a[6]), packf2(a[3], a[7]));
            g_QQ[i] = make_ulonglong2(packf2(a[0], a[4]), packf2(a[1], a[5]));
            g_KK[i] = kk;
            sKxy[row] = kk;
            unsigned bp = qbins(a[0], a[1], a[4], a[5]);
            g_binPS[i] = bp;
            g_Vop[i] = a[8]; g_Varg[i] = a[9]; g_Vstk[i] = a[10];
            push_query(i, bp);
        }
    }
    __syncthreads();

    // per-bin partial max over own 64 keys, ALL 128 bins: 512 thr = 128x4
    {
        const int mybin = tid >> 2, q = tid & 3;
        const float thc = -PI_F + (mybin + 0.5f) * DLT;
        const float ux = cosf(thc), uy = sinf(thc);
        const unsigned long long ua = packf2(ux, ux), ub = packf2(uy, uy);
        float mP = -FLT_MAX, mS = -FLT_MAX;
#pragma unroll
        for (int k = 0; k < RPB / 4; k++) {
            ulonglong2 kk = sKxy[q * (RPB / 4) + k];
            unsigned long long s = fma2(ua, kk.x, mul2(ub, kk.y));
            mP = fmaxf(mP, lo32(s));
            mS = fmaxf(mS, hi32(s));
        }
        mP = fmaxf(mP, __shfl_down_sync(0xffffffffu, mP, 1));
        mS = fmaxf(mS, __shfl_down_sync(0xffffffffu, mS, 1));
        mP = fmaxf(mP, __shfl_down_sync(0xffffffffu, mP, 2));
        mS = fmaxf(mS, __shfl_down_sync(0xffffffffu, mS, 2));
        if (q == 0) {
            g_sPartP[mybin * NB + b] = mP;
            g_sPartS[mybin * NB + b] = mS;
        }
    }
    // per-block |k|^2 max (both heads)
    if (tid < RPB) {
        ulonglong2 kk = sKxy[tid];
        unsigned long long n2 = fma2(kk.x, kk.x, mul2(kk.y, kk.y));
        float np = lo32(n2), ns = hi32(n2);
#pragma unroll
        for (int off = 16; off; off >>= 1) {
            np = fmaxf(np, __shfl_xor_sync(0xffffffffu, np, off));
            ns = fmaxf(ns, __shfl_xor_sync(0xffffffffu, ns, off));
        }
        if (lane == 0) { sn2w[0][tid >> 5] = np; sn2w[1][tid >> 5] = ns; }
    }
    __syncthreads();
    if (tid == 0) {
        g_n2P[b] = fmaxf(sn2w[0][0], sn2w[0][1]);
        g_n2S[b] = fmaxf(sn2w[1][0], sn2w[1][1]);
    }
}

// ---------------------------------------------------------------------------
// K2: one block per bin. TWO-LEVEL collect: a K1 block g can contain a
// candidate for bin b IFF partial[b,g] >= thresh[b] (the partial is the max
// of exactly the s_u values the collect recomputes — identical fma2/cosf
// inputs across kernels => bit-identical). So scan ONLY the selected
// slices (~1-4 of 128) instead of all T keys.
// ---------------------------------------------------------------------------
__global__ __launch_bounds__(K2TH) void bin_query_kernel(float* __restrict__ out, int T) {
    __shared__ float sPartP[NB], sPartS[NB];
    __shared__ int sBlkP[NB], sBlkS[NB];
    __shared__ int sNblk[2];
    __shared__ int scandP[CAP], scandS[CAP];
    __shared__ ulonglong2 sKP[CAP], sKS[CAP];
    __shared__ float sVop[CAP], sVarg[CAP], sVstk[CAP];
    __shared__ int scnt[2];
    __shared__ float sredP[4], sredS[4], sredNP[4], sredNS[4];
    __shared__ float sth[2];
    __shared__ int sqlP[CAPQ], sqlS[CAPQ];

    const int b = blockIdx.x;
    const int tid = threadIdx.x, lane = tid & 31, w = tid >> 5;
    const float DLT = TWO_PI_F / NB;
    const float thb = -PI_F + (b + 0.5f) * DLT;
    const float ux = cosf(thb), uy = sinf(thb);
    const unsigned long long ua = packf2(ux, ux), ub = packf2(uy, uy);

    // ---- early independent loads: query lists (overlap with threshold) ----
    const int totP = g_qcnt[b], totS = g_qcnt[NB + b];
    const int nqP = min(totP, CAPQ), nqS = min(totS, CAPQ);
    for (int t = tid; t < nqP; t += K2TH) sqlP[t] = g_qlistP[b * CAPQ + t];
    for (int t = tid; t < nqS; t += K2TH) sqlS[t] = g_qlistS[b * CAPQ + t];
    if (tid == 0) { scnt[0] = 0; scnt[1] = 0; sNblk[0] = 0; sNblk[1] = 0; }

    // ---- threshold from partials (keep partials in smem for selection) ----
    if (tid < NB) {
        float vp = g_sPartP[b * NB + tid];
        float vs = g_sPartS[b * NB + tid];
        sPartP[tid] = vp; sPartS[tid] = vs;
        float np = g_n2P[tid];
        float ns = g_n2S[tid];
#pragma unroll
        for (int off = 16; off; off >>= 1) {
            vp = fmaxf(vp, __shfl_xor_sync(0xffffffffu, vp, off));
            vs = fmaxf(vs, __shfl_xor_sync(0xffffffffu, vs, off));
            np = fmaxf(np, __shfl_xor_sync(0xffffffffu, np, off));
            ns = fmaxf(ns, __shfl_xor_sync(0xffffffffu, ns, off));
        }
        if (lane == 0) { sredP[w] = vp; sredS[w] = vs; sredNP[w] = np; sredNS[w] = ns; }
    }
    __syncthreads();
    if (tid == 0) {
        float MP = fmaxf(fmaxf(sredP[0], sredP[1]), fmaxf(sredP[2], sredP[3]));
        float MS = fmaxf(fmaxf(sredS[0], sredS[1]), fmaxf(sredS[2], sredS[3]));
        float NP = fmaxf(fmaxf(sredNP[0], sredNP[1]), fmaxf(sredNP[2], sredNP[3]));
        float NS = fmaxf(fmaxf(sredNS[0], sredNS[1]), fmaxf(sredNS[2], sredNS[3]));
        // Exact-cover threshold (proven rounds 4/6/7/8/11): argmax key of any
        // direction in this bin has s_u >= M - Kmax*DLT; 1.25 absorbs fp slop.
        sth[0] = MP - 1.25f * sqrtf(NP) * DLT;
        sth[1] = MS - 1.25f * sqrtf(NS) * DLT;
    }
    __syncthreads();
    const float tP = sth[0], tS = sth[1];

    // ---- select hot slices: block g is hot iff partial[b,g] >= thresh ----
    if (tid < NB) {
        if (sPartP[tid] >= tP) { int p = atomicAdd(&sNblk[0], 1); sBlkP[p] = tid; }
        if (sPartS[tid] >= tS) { int p = atomicAdd(&sNblk[1], 1); sBlkS[p] = tid; }
    }
    __syncthreads();
    const int nbP = sNblk[0], nbS = sNblk[1];

    // ---- collect candidates from hot slices only ----
    for (int idx = tid; idx < nbP * RPB; idx += K2TH) {
        const int j = sBlkP[idx >> 6] * RPB + (idx & (RPB - 1));
        ulonglong2 kk = g_KK[j];
        unsigned long long s = fma2(ua, kk.x, mul2(ub, kk.y));
        if (lo32(s) >= tP) { int p = atomicAdd(&scnt[0], 1); if (p < CAP) scandP[p] = j; }
    }
    for (int idx = tid; idx < nbS * RPB; idx += K2TH) {
        const int j = sBlkS[idx >> 6] * RPB + (idx & (RPB - 1));
        ulonglong2 kk = g_KK[j];
        unsigned long long s = fma2(ua, kk.x, mul2(ub, kk.y));
        if (hi32(s) >= tS) { int p = atomicAdd(&scnt[1], 1); if (p < CAP) scandS[p] = j; }
    }
    __syncthreads();
    const int nP = min(scnt[0], CAP), nS = min(scnt[1], CAP);
    for (int t = tid; t < nP; t += K2TH) {
        int c = scandP[t];
        sKP[t] = g_KK[c]; sVop[t] = g_Vop[c]; sVarg[t] = g_Varg[c];
    }
    for (int t = tid; t < nS; t += K2TH) {
        int c = scandS[t];
        sKS[t] = g_KK[c]; sVstk[t] = g_Vstk[c];
    }
    __syncthreads();

    // ---- resolve this bin's queries (exact fp32 + first-index tie-break) --
    for (int t = tid; t < nqP; t += K2TH) {
        const int i = sqlP[t];
        ulonglong2 q = g_QQ[i];
        const float qx = lo32(q.x), qy = lo32(q.y);
        float best = -FLT_MAX; int bi = 0x7fffffff, bt = 0;
        for (int c = 0; c < nP; c++) {
            int kj = scandP[c];
            ulonglong2 k2 = sKP[c];
            float sc = fmaf(qx, lo32(k2.x), __fmul_rn(qy, lo32(k2.y)));
            if (sc > best || (sc == best && kj < bi)) { best = sc; bi = kj; bt = c; }
        }
        out[i]     = sVop[bt];
        out[T + i] = sVarg[bt];
    }
    for (int t = tid; t < nqS; t += K2TH) {
        const int i = sqlS[t];
        ulonglong2 q = g_QQ[i];
        const float qx = hi32(q.x), qy = hi32(q.y);
        float best = -FLT_MAX; int bi = 0x7fffffff, bt = 0;
        for (int c = 0; c < nS; c++) {
            int kj = scandS[c];
            ulonglong2 k2 = sKS[c];
            float sc = fmaf(qx, hi32(k2.x), __fmul_rn(qy, hi32(k2.y)));
            if (sc > best || (sc == best && kj < bi)) { best = sc; bi = kj; bt = c; }
        }
        out[2 * T + i] = sVstk[bt];
    }

    // exact fallback if a query list overflowed (never expected; idempotent)
    if (totP > CAPQ) {
        for (int j = tid; j < T; j += K2TH) {
            if ((g_binPS[j] & 0xffffu) == (unsigned)b) {
                ulonglong2 q = g_QQ[j];
                const float qx = lo32(q.x), qy = lo32(q.y);
                float best = -FLT_MAX; int bi = 0x7fffffff, bt = 0;
                for (int c = 0; c < nP; c++) {
                    int kj = scandP[c];
                    ulonglong2 k2 = sKP[c];
                    float sc = fmaf(qx, lo32(k2.x), __fmul_rn(qy, lo32(k2.y)));
                    if (sc > best || (sc == best && kj < bi)) { best = sc; bi = kj; bt = c; }
                }
                out[j]     = sVop[bt];
                out[T + j] = sVarg[bt];
            }
        }
    }
    if (totS > CAPQ) {
        for (int j = tid; j < T; j += K2TH) {
            if ((g_binPS[j] >> 16) == (unsigned)b) {
                ulonglong2 q = g_QQ[j];
                const float qx = hi32(q.x), qy = hi32(q.y);
                float best = -FLT_MAX; int bi = 0x7fffffff, bt = 0;
                for (int c = 0; c < nS; c++) {
                    int kj = scandS[c];
                    ulonglong2 k2 = sKS[c];
                    float sc = fmaf(qx, hi32(k2.x), __fmul_rn(qy, hi32(k2.y)));
                    if (sc > best || (sc == best && kj < bi)) { best = sc; bi = kj; bt = c; }
                }
                out[2 * T + j] = sVstk[bt];
            }
        }
    }

    __syncthreads();
    if (tid == 0) { g_qcnt[b] = 0; g_qcnt[NB + b] = 0; }   // self-reset
}

// ---------------------------------------------------------------------------
// Generic fallback (D != 36 or T != MAXT): projection + brute-force argmax.
// ---------------------------------------------------------------------------
__global__ void proj_generic_kernel(
        const float* __restrict__ emb,
        const float* __restrict__ wqp, const float* __restrict__ wkp,
        const float* __restrict__ wvop, const float* __restrict__ wvarg,
        const float* __restrict__ wqs, const float* __restrict__ wks,
        const float* __restrict__ wvs, int T, int D) {
    extern __shared__ float sw[];
    const int tid = threadIdx.x;
    for (int k = tid; k < 2 * D; k += blockDim.x) {
        sw[k]         = wqp[k];
        sw[2 * D + k] = wkp[k];
        sw[4 * D + k] = wqs[k];
        sw[6 * D + k] = wks[k];
    }
    for (int k = tid; k < D; k += blockDim.x) {
        sw[8 * D + k]  = wvop[k];
        sw[9 * D + k]  = wvarg[k];
        sw[10 * D + k] = wvs[k];
    }
    __syncthreads();
    int i = blockIdx.x * blockDim.x + tid;
    if (i >= T) return;
    const float* e = emb + (size_t)i * D;
    float a[11];
#pragma unroll
    for (int c = 0; c < 11; c++) a[c] = 0.f;
    for (int d = 0; d < D; d++) {
        float ev = e[d];
#pragma unroll
        for (int c = 0; c < 11; c++) a[c] = fmaf(ev, sw[c * D + d], a[c]);
    }
    g_QQ[i] = make_ulonglong2(packf2(a[0], a[4]), packf2(a[1], a[5]));
    g_KK[i] = make_ulonglong2(packf2(a[2], a[6]), packf2(a[3], a[7]));
    g_Vop[i] = a[8]; g_Varg[i] = a[9]; g_Vstk[i] = a[10];
}

__global__ void brute_generic_kernel(float* __restrict__ out, int T) {
    const int gidx = blockIdx.x * blockDim.x + threadIdx.x;
    const int i = gidx >> 1, head = gidx & 1;
    if (i >= T) return;
    ulonglong2 q = g_QQ[i];
    const float qx = head ? hi32(q.x) : lo32(q.x);
    const float qy = head ? hi32(q.y) : lo32(q.y);
    float best = -FLT_MAX; int bi = 0;
    for (int j = 0; j < T; j++) {
        ulonglong2 k2 = g_KK[j];
        float kx = head ? hi32(k2.x) : lo32(k2.x);
        float ky = head ? hi32(k2.y) : lo32(k2.y);
        float sc = fmaf(qx, kx, __fmul_rn(qy, ky));
        if (sc > best) { best = sc; bi = j; }
    }
    if (head == 0) {
        out[i]     = g_Vop[bi];
        out[T + i] = g_Varg[bi];
    } else {
        out[2 * T + i] = g_Vstk[bi];
    }
}

extern "C" void kernel_launch(void* const* d_in, const int* in_sizes, int n_in,
                              void* d_out, int out_size) {
    const float* emb   = (const float*)d_in[0];
    const float* wqp   = (const float*)d_in[1];
    const float* wkp   = (const float*)d_in[2];
    const float* wvop  = (const float*)d_in[3];
    const float* wvarg = (const float*)d_in[4];
    const float* wqs   = (const float*)d_in[5];
    const float* wks   = (const float*)d_in[6];
    const float* wvs   = (const float*)d_in[7];
    float* out = (float*)d_out;

    const int D = in_sizes[1] / 2;   // WQ_prog is (2, D)
    const int T = in_sizes[0] / D;   // embeddings is (T, D)

    if (D == PD && T == MAXT) {
        proj_part_kernel<<<NB, K1TH>>>(emb, wqp, wkp, wvop, wvarg, wqs, wks, wvs);
        bin_query_kernel<<<NB, K2TH>>>(out, T);
    } else {
        const int pb = (T + 255) / 256;
        proj_generic_kernel<<<pb, 256, (size_t)(11 * D) * sizeof(float)>>>(
            emb, wqp, wkp, wvop, wvarg, wqs, wks, wvs, T, D);
        brute_generic_kernel<<<(2 * T + 255) / 256, 256>>>(out, T);
    }
}